// round 8
// baseline (speedup 1.0000x reference)
#include <cuda_runtime.h>
#include <cuda_bf16.h>
#include <cstdint>
#include <string.h>

typedef unsigned long long ull;
typedef unsigned int uint;

#define L    64
#define NGR  8192
#define HD   128
#define MM   64             // graphs per CTA (recurrence) / rows per CTA (xg)
#define NTH  512            // 16 warps
#define NROW (NGR * L)      // 524288 x-rows

// ---- smem byte offsets (A tiles K=128 now: 16KB each) ----
#define S_AHI  0
#define S_ALO  16384
#define S_WB0  32768        // W image buf 0 (64KB)
#define S_WB1  98304        // W image buf 1 (64KB)
#define S_BIAS 163840       // 512 floats (xg kernel only)
#define S_TOT  165888

// W images: [job = kc*2 + split][512 n][64 k] bf16, SW128 blocked. 4 x 64KB each.
__device__ __align__(128) unsigned char wblob_ih[4 * 65536];
__device__ __align__(128) unsigned char wblob_hh[4 * 65536];
__device__ float xg_buf[(size_t)NROW * 512];     // 1GB: x@W_ih^T + bias
__device__ float hs_buf[(size_t)NGR * L * HD];   // 256MB hidden states

// ---- PTX helpers (base PTX only; no tcgen05 on this toolchain) ----
__device__ __forceinline__ uint smem_u32(const void* p) {
    uint a; asm("{ .reg .u64 t; cvta.to.shared.u64 t, %1; cvt.u32.u64 %0, t; }"
                : "=r"(a) : "l"(p));
    return a;
}
#define CP_ASYNC16(dst, src) \
    asm volatile("cp.async.cg.shared.global [%0], [%1], 16;" :: "r"(dst), "l"(src))
#define CP_COMMIT() asm volatile("cp.async.commit_group;" ::: "memory")
#define CP_WAIT(n)  asm volatile("cp.async.wait_group %0;" :: "n"(n) : "memory")

__device__ __forceinline__ void ldmx4(uint* r, uint addr) {
    asm volatile("ldmatrix.sync.aligned.m8n8.x4.shared.b16 {%0,%1,%2,%3}, [%4];"
        : "=r"(r[0]), "=r"(r[1]), "=r"(r[2]), "=r"(r[3]) : "r"(addr));
}
// W stored K-major: non-trans ldmatrix yields the .col B fragment directly.
__device__ __forceinline__ void ldmx2(uint* r, uint addr) {
    asm volatile("ldmatrix.sync.aligned.m8n8.x2.shared.b16 {%0,%1}, [%2];"
        : "=r"(r[0]), "=r"(r[1]) : "r"(addr));
}
__device__ __forceinline__ void mma16816(float* d, const uint* a, const uint* b) {
    asm volatile(
        "mma.sync.aligned.m16n8k16.row.col.f32.bf16.bf16.f32 "
        "{%0,%1,%2,%3}, {%4,%5,%6,%7}, {%8,%9}, {%0,%1,%2,%3};"
        : "+f"(d[0]), "+f"(d[1]), "+f"(d[2]), "+f"(d[3])
        : "r"(a[0]), "r"(a[1]), "r"(a[2]), "r"(a[3]), "r"(b[0]), "r"(b[1]));
}
// ---- MUFU activations (rel err ~1e-7) ----
__device__ __forceinline__ float ex2a(float x) { float y; asm("ex2.approx.f32 %0, %1;" : "=f"(y) : "f"(x)); return y; }
__device__ __forceinline__ float rcpa(float x) { float y; asm("rcp.approx.f32 %0, %1;" : "=f"(y) : "f"(x)); return y; }
__device__ __forceinline__ float sigf(float x)  { return rcpa(1.0f + ex2a(-1.4426950408889634f * x)); }
__device__ __forceinline__ float tanhf_(float x){ return fmaf(2.0f, rcpa(1.0f + ex2a(-2.8853900817779268f * x)), -1.0f); }

__device__ __forceinline__ uint pk2bf(float a, float b) {
    __nv_bfloat162 p(__float2bfloat16(a), __float2bfloat16(b));
    uint u; memcpy(&u, &p, 4); return u;
}
// A tile: 64 rows x 128 k bf16; atoms 8r x 64k; SW128 swizzle (16KB)
__device__ __forceinline__ uint a_off(int r, int k) {
    uint b = (uint)((((r >> 3) + (k >> 6) * 8) << 10) + ((r & 7) << 7) + ((k & 63) << 1));
    return b ^ ((b >> 3) & 0x70);
}
// W image: 512 n x 64 k bf16; atoms 8n x 64k (64KB)
__device__ __forceinline__ uint w_off(int n, int k) {
    uint b = (uint)(((n >> 3) << 10) + ((n & 7) << 7) + (k << 1));
    return b ^ ((b >> 3) & 0x70);
}

// ============ W prep: split hi/lo, swizzle W_ih and W_hh (K=128 -> 4 images) ============
extern "C" __global__ void prep_kernel(const float* __restrict__ W_ih,
                                       const float* __restrict__ W_hh)
{
    int i = blockIdx.x * blockDim.x + threadIdx.x;   // 2 * 512 * 128
    if (i >= 2 * 512 * 128) return;
    int wsel = i >> 16;
    int r = i & 65535;
    int n = r >> 7, k = r & 127;
    const float* W = wsel ? W_hh : W_ih;
    unsigned char* blob = wsel ? wblob_hh : wblob_ih;
    float w = W[n * 128 + k];
    __nv_bfloat16 hi = __float2bfloat16(w);
    __nv_bfloat16 lo = __float2bfloat16(w - __bfloat162float(hi));
    int kc = k >> 6;
    uint off = w_off(n, k & 63);
    *(__nv_bfloat16*)(blob + (size_t)(kc * 2 + 0) * 65536 + off) = hi;
    *(__nv_bfloat16*)(blob + (size_t)(kc * 2 + 1) * 65536 + off) = lo;
}

// ============ xg = x @ W_ih^T + (b_ih + b_hh) : dependence-free GEMM ============
extern "C" __global__ void __launch_bounds__(NTH, 1)
xg_kernel(const float* __restrict__ x,
          const float* __restrict__ b_ih,
          const float* __restrict__ b_hh)
{
    extern __shared__ __align__(1024) char sm[];
    const uint smb  = smem_u32(sm);
    const int tid   = threadIdx.x;
    const int lane  = tid & 31;
    const int warp  = tid >> 5;
    const size_t row0 = (size_t)blockIdx.x * MM;
    float* Bi = (float*)(sm + S_BIAS);

    if (tid < 512) Bi[tid] = b_ih[tid] + b_hh[tid];

    // prefetch W image 0
    {
        const char* src = (const char*)wblob_ih + tid * 16;
        uint dst = smb + S_WB0 + tid * 16;
        #pragma unroll
        for (int it = 0; it < 8; it++)
            CP_ASYNC16(dst + it * 8192, src + it * 8192);
        CP_COMMIT();
    }
    // stage x rows (64 x 128 fp32) -> A hi/lo
    #pragma unroll
    for (int it = 0; it < 4; it++) {
        int idx = tid + it * NTH;
        int g = idx >> 5, v = idx & 31;
        float4 xv = *(const float4*)(x + (row0 + g) * HD + v * 4);
        float fx = __bfloat162float(__float2bfloat16(xv.x));
        float fy = __bfloat162float(__float2bfloat16(xv.y));
        float fz = __bfloat162float(__float2bfloat16(xv.z));
        float fw = __bfloat162float(__float2bfloat16(xv.w));
        uint off = a_off(g, v * 4);
        *(ull*)(sm + S_AHI + off) = (ull)pk2bf(fx, fy) | ((ull)pk2bf(fz, fw) << 32);
        *(ull*)(sm + S_ALO + off) =
            (ull)pk2bf(xv.x - fx, xv.y - fy) | ((ull)pk2bf(xv.z - fz, xv.w - fw) << 32);
    }
    __syncthreads();   // Bi + A staged

    // ---- fragment address components (identical scheme to recurrence) ----
    const int rA    = (lane & 7);
    const int mHalf = (lane >> 3) & 1;
    const int aKsel = (lane >> 4) << 4;
    const uint aPre = (uint)(rA << 7);
    const uint swA  = (uint)(rA << 4);
    const int lb    = lane & 15;
    const uint bPre = (uint)((lb & 7) << 7) + ((uint)warp << 10);
    const uint swB  = (uint)((lb & 7) << 4);
    const int bKsel = ((lb >> 3) & 1) << 4;
    const int jj   = (lane & 3) << 1;
    const int j0   = (warp << 3) + jj;
    const int rowq = lane >> 2;

    float acc[4][4][4];
    #pragma unroll
    for (int gt = 0; gt < 4; gt++) {
        float b0 = Bi[gt * 128 + j0], b1 = Bi[gt * 128 + j0 + 1];
        #pragma unroll
        for (int mt = 0; mt < 4; mt++) {
            acc[mt][gt][0] = b0; acc[mt][gt][1] = b1;
            acc[mt][gt][2] = b0; acc[mt][gt][3] = b1;
        }
    }

    for (int j = 0; j < 4; j++) {
        if (j + 1 < 4) {
            const char* src = (const char*)wblob_ih + (size_t)(j + 1) * 65536 + tid * 16;
            uint dst = smb + ((j + 1) & 1 ? S_WB1 : S_WB0) + tid * 16;
            #pragma unroll
            for (int it = 0; it < 8; it++)
                CP_ASYNC16(dst + it * 8192, src + it * 8192);
            CP_COMMIT();
            CP_WAIT(1);
        } else {
            CP_WAIT(0);
        }
        __syncthreads();

        const int kc = j >> 1, s = j & 1;
        const uint wb = smb + ((j & 1) ? S_WB1 : S_WB0);
        const uint aAtomBase = (uint)((mHalf + kc * 8) << 10);

        #pragma unroll
        for (int ks = 0; ks < 4; ks++) {
            uint bfr[4][2];
            const uint bLow = (uint)((ks << 5) + bKsel) ^ swB;
            #pragma unroll
            for (int gt = 0; gt < 4; gt++)
                ldmx2(bfr[gt], wb + (uint)(gt << 14) + bPre + bLow);
            const uint aLow = (uint)((ks << 5) + aKsel) ^ swA;
            #pragma unroll
            for (int mt = 0; mt < 4; mt++) {
                uint ah[4];
                uint aoff = aAtomBase + (uint)(mt << 11) + aPre + aLow;
                ldmx4(ah, smb + S_AHI + aoff);
                if (s == 0) {
                    uint al[4];
                    ldmx4(al, smb + S_ALO + aoff);
                    #pragma unroll
                    for (int gt = 0; gt < 4; gt++) {
                        mma16816(acc[mt][gt], ah, bfr[gt]);
                        mma16816(acc[mt][gt], al, bfr[gt]);
                    }
                } else {
                    #pragma unroll
                    for (int gt = 0; gt < 4; gt++)
                        mma16816(acc[mt][gt], ah, bfr[gt]);
                }
            }
        }
        __syncthreads();
    }

    // ---- write xg (fp32) ----
    #pragma unroll
    for (int mt = 0; mt < 4; mt++)
        #pragma unroll
        for (int rg = 0; rg < 2; rg++) {
            const size_t row = row0 + mt * 16 + rg * 8 + rowq;
            #pragma unroll
            for (int gt = 0; gt < 4; gt++)
                *(float2*)(xg_buf + row * 512 + gt * 128 + j0)
                    = make_float2(acc[mt][gt][rg * 2], acc[mt][gt][rg * 2 + 1]);
        }
}

// ============ recurrence: gates = xg + h @ W_hh^T ============
extern "C" __global__ void __launch_bounds__(NTH, 1)
lstm_mma_kernel()
{
    extern __shared__ __align__(1024) char sm[];
    const uint smb  = smem_u32(sm);
    const int tid   = threadIdx.x;
    const int lane  = tid & 31;
    const int warp  = tid >> 5;
    const int graph0 = blockIdx.x * MM;

    const int rA    = (lane & 7);
    const int mHalf = (lane >> 3) & 1;
    const int aKsel = (lane >> 4) << 4;
    const uint aPre = (uint)(rA << 7);
    const uint swA  = (uint)(rA << 4);
    const int lb    = lane & 15;
    const uint bPre = (uint)((lb & 7) << 7) + ((uint)warp << 10);
    const uint swB  = (uint)((lb & 7) << 4);
    const int bKsel = ((lb >> 3) & 1) << 4;
    const int jj   = (lane & 3) << 1;
    const int j0   = (warp << 3) + jj;
    const int rowq = lane >> 2;

    float creg[4][4];
    #pragma unroll
    for (int a = 0; a < 4; a++)
        #pragma unroll
        for (int b = 0; b < 4; b++) creg[a][b] = 0.0f;

    for (int t = 0; t < L; t++) {
        if (t > 0) {   // prefetch W_hh image 0 (overlaps xg seed loads)
            const char* src = (const char*)wblob_hh + tid * 16;
            uint dst = smb + S_WB0 + tid * 16;
            #pragma unroll
            for (int it = 0; it < 8; it++)
                CP_ASYNC16(dst + it * 8192, src + it * 8192);
            CP_COMMIT();
        }

        // ---- seed accumulators from xg (bias folded in) ----
        float acc[4][4][4];
        #pragma unroll
        for (int mt = 0; mt < 4; mt++)
            #pragma unroll
            for (int rg = 0; rg < 2; rg++) {
                const int m = mt * 16 + rg * 8 + rowq;
                const float* base = xg_buf + ((size_t)(graph0 + m) * L + t) * 512 + j0;
                #pragma unroll
                for (int gt = 0; gt < 4; gt++) {
                    float2 v = __ldg((const float2*)(base + gt * 128));
                    acc[mt][gt][rg * 2]     = v.x;
                    acc[mt][gt][rg * 2 + 1] = v.y;
                }
            }

        if (t > 0) {
            for (int j = 0; j < 4; j++) {
                if (j + 1 < 4) {
                    const char* src = (const char*)wblob_hh + (size_t)(j + 1) * 65536 + tid * 16;
                    uint dst = smb + ((j + 1) & 1 ? S_WB1 : S_WB0) + tid * 16;
                    #pragma unroll
                    for (int it = 0; it < 8; it++)
                        CP_ASYNC16(dst + it * 8192, src + it * 8192);
                    CP_COMMIT();
                    CP_WAIT(1);
                } else {
                    CP_WAIT(0);
                }
                __syncthreads();   // image j ready; prior-step A writes visible (j==0)

                const int kc = j >> 1, s = j & 1;
                const uint wb = smb + ((j & 1) ? S_WB1 : S_WB0);
                const uint aAtomBase = (uint)((mHalf + kc * 8) << 10);

                #pragma unroll
                for (int ks = 0; ks < 4; ks++) {
                    uint bfr[4][2];
                    const uint bLow = (uint)((ks << 5) + bKsel) ^ swB;
                    #pragma unroll
                    for (int gt = 0; gt < 4; gt++)
                        ldmx2(bfr[gt], wb + (uint)(gt << 14) + bPre + bLow);
                    const uint aLow = (uint)((ks << 5) + aKsel) ^ swA;
                    #pragma unroll
                    for (int mt = 0; mt < 4; mt++) {
                        uint ah[4];
                        uint aoff = aAtomBase + (uint)(mt << 11) + aPre + aLow;
                        ldmx4(ah, smb + S_AHI + aoff);
                        if (s == 0) {
                            uint al[4];
                            ldmx4(al, smb + S_ALO + aoff);
                            #pragma unroll
                            for (int gt = 0; gt < 4; gt++) {
                                mma16816(acc[mt][gt], ah, bfr[gt]);
                                mma16816(acc[mt][gt], al, bfr[gt]);
                            }
                        } else {
                            #pragma unroll
                            for (int gt = 0; gt < 4; gt++)
                                mma16816(acc[mt][gt], ah, bfr[gt]);
                        }
                    }
                }
                __syncthreads();   // buffer free for next copy
            }
        }

        // ---- epilogue: lane-local LSTM update; h -> A smem + hs_buf ----
        #pragma unroll
        for (int mt = 0; mt < 4; mt++) {
            #pragma unroll
            for (int rg = 0; rg < 2; rg++) {
                float h2[2];
                #pragma unroll
                for (int cp = 0; cp < 2; cp++) {
                    const int fr = rg * 2 + cp;
                    float iv = sigf (acc[mt][0][fr]);
                    float fv = sigf (acc[mt][1][fr]);
                    float gv = tanhf_(acc[mt][2][fr]);
                    float ov = sigf (acc[mt][3][fr]);
                    float c  = fv * creg[mt][fr] + iv * gv;
                    creg[mt][fr] = c;
                    h2[cp] = ov * tanhf_(c);
                }
                const int g = mt * 16 + rg * 8 + rowq;
                float f0 = __bfloat162float(__float2bfloat16(h2[0]));
                float f1 = __bfloat162float(__float2bfloat16(h2[1]));
                uint off = a_off(g, j0);
                *(uint*)(sm + S_AHI + off) = pk2bf(f0, f1);
                *(uint*)(sm + S_ALO + off) = pk2bf(h2[0] - f0, h2[1] - f1);
                *(float2*)(hs_buf + ((size_t)(graph0 + g) * L + t) * HD + j0)
                    = make_float2(h2[0], h2[1]);
            }
        }
        __syncthreads();   // A writes visible before next step's MMAs
    }
}

// ============ attention pooling over hs_buf ============
extern "C" __global__ void __launch_bounds__(256)
att_kernel(const float* __restrict__ W_att, const float* __restrict__ b_att,
           float* __restrict__ out)
{
    __shared__ float Wa[HD];
    __shared__ float Sc[32 * L];
    const int tid = threadIdx.x, lane = tid & 31, warp = tid >> 5;
    const int graph0 = blockIdx.x * 32;
    const int g0 = warp << 2;
    if (tid < HD) Wa[tid] = W_att[tid];
    const float batt = b_att[0];
    __syncthreads();

    #pragma unroll 1
    for (int r = 0; r < 4; r++) {
        const int g = g0 + r;
        const size_t gg = (size_t)(graph0 + g);
        const float* hp = hs_buf + gg * L * HD;
        const float4 wv = *(const float4*)(Wa + lane * 4);
        for (int t = 0; t < L; t++) {
            float4 hv = *(const float4*)(hp + t * HD + lane * 4);
            float d = hv.x * wv.x + hv.y * wv.y + hv.z * wv.z + hv.w * wv.w;
            #pragma unroll
            for (int o = 16; o; o >>= 1)
                d += __shfl_xor_sync(0xffffffffu, d, o);
            if (lane == 0) Sc[g * L + t] = d + batt;
        }
        __syncwarp();
        float s1 = Sc[g * L + lane], s2 = Sc[g * L + 32 + lane];
        float m = fmaxf(s1, s2);
        #pragma unroll
        for (int o = 16; o; o >>= 1)
            m = fmaxf(m, __shfl_xor_sync(0xffffffffu, m, o));
        float e1 = ex2a(1.4426950408889634f * (s1 - m));
        float e2 = ex2a(1.4426950408889634f * (s2 - m));
        float z = e1 + e2;
        #pragma unroll
        for (int o = 16; o; o >>= 1)
            z += __shfl_xor_sync(0xffffffffu, z, o);
        float inv = rcpa(z);
        Sc[g * L + lane] = e1 * inv;
        Sc[g * L + 32 + lane] = e2 * inv;
        __syncwarp();
        float a0 = 0.f, a1 = 0.f, a2 = 0.f, a3 = 0.f;
        for (int tt = 0; tt < L; tt++) {
            float wt = Sc[g * L + tt];
            a0 = fmaf(wt, hp[tt * HD +  0 + lane], a0);
            a1 = fmaf(wt, hp[tt * HD + 32 + lane], a1);
            a2 = fmaf(wt, hp[tt * HD + 64 + lane], a2);
            a3 = fmaf(wt, hp[tt * HD + 96 + lane], a3);
        }
        float* op = out + gg * HD;
        op[ 0 + lane] = a0;
        op[32 + lane] = a1;
        op[64 + lane] = a2;
        op[96 + lane] = a3;
    }
}

extern "C" void kernel_launch(void* const* d_in, const int* in_sizes, int n_in,
                              void* d_out, int out_size)
{
    const float* x     = (const float*)d_in[0];
    // d_in[1] = batch (arange(N)//L), unused
    const float* W_ih  = (const float*)d_in[2];
    const float* W_hh  = (const float*)d_in[3];
    const float* b_ih  = (const float*)d_in[4];
    const float* b_hh  = (const float*)d_in[5];
    const float* W_att = (const float*)d_in[6];
    const float* b_att = (const float*)d_in[7];
    float* out = (float*)d_out;

    prep_kernel<<<512, 256>>>(W_ih, W_hh);
    cudaFuncSetAttribute(xg_kernel,
                         cudaFuncAttributeMaxDynamicSharedMemorySize, S_TOT);
    cudaFuncSetAttribute(lstm_mma_kernel,
                         cudaFuncAttributeMaxDynamicSharedMemorySize, S_TOT);
    xg_kernel<<<NROW / MM, NTH, S_TOT>>>(x, b_ih, b_hh);
    lstm_mma_kernel<<<NGR / MM, NTH, S_TOT>>>();
    att_kernel<<<NGR / 32, 256>>>(W_att, b_att, out);
}

// round 10
// speedup vs baseline: 1.3610x; 1.3610x over previous
#include <cuda_runtime.h>
#include <cuda_fp16.h>
#include <cstdint>
#include <string.h>

typedef unsigned long long ull;
typedef unsigned int uint;

#define L    64
#define NGR  8192
#define HD   128
#define MM   64             // graphs per CTA
#define NTH  512            // 16 warps

// ---- smem byte offsets ----
#define S_A    0            // A: 64 rows x 256 k fp16, SW128 blocked (32KB)
#define S_WB0  32768        // W image buf 0 (64KB)
#define S_WB1  98304        // W image buf 1 (64KB)
#define S_TOT  163840

// W images: 8 jobs (k32 slices of K=256). Each: [512 n][64 kcol] fp16,
// kcol 0..31 = Whi slice, kcol 32..63 = Wlo slice. SW128 blocked. 64KB each.
__device__ __align__(128) unsigned char wblob[8 * 65536];
__device__ float hs_buf[(size_t)NGR * L * HD];   // 256MB hidden states

// ---- PTX helpers (base PTX; no tcgen05 on this toolchain) ----
__device__ __forceinline__ uint smem_u32(const void* p) {
    uint a; asm("{ .reg .u64 t; cvta.to.shared.u64 t, %1; cvt.u32.u64 %0, t; }"
                : "=r"(a) : "l"(p));
    return a;
}
#define CP_ASYNC16(dst, src) \
    asm volatile("cp.async.cg.shared.global [%0], [%1], 16;" :: "r"(dst), "l"(src))
#define CP_COMMIT() asm volatile("cp.async.commit_group;" ::: "memory")
#define CP_WAIT(n)  asm volatile("cp.async.wait_group %0;" :: "n"(n) : "memory")

__device__ __forceinline__ void ldmx4(uint* r, uint addr) {
    asm volatile("ldmatrix.sync.aligned.m8n8.x4.shared.b16 {%0,%1,%2,%3}, [%4];"
        : "=r"(r[0]), "=r"(r[1]), "=r"(r[2]), "=r"(r[3]) : "r"(addr));
}
// W stored K-major: non-trans ldmatrix yields the .col B fragment directly.
__device__ __forceinline__ void ldmx2(uint* r, uint addr) {
    asm volatile("ldmatrix.sync.aligned.m8n8.x2.shared.b16 {%0,%1}, [%2];"
        : "=r"(r[0]), "=r"(r[1]) : "r"(addr));
}
__device__ __forceinline__ void mma16816(float* d, const uint* a, const uint* b) {
    asm volatile(
        "mma.sync.aligned.m16n8k16.row.col.f32.f16.f16.f32 "
        "{%0,%1,%2,%3}, {%4,%5,%6,%7}, {%8,%9}, {%0,%1,%2,%3};"
        : "+f"(d[0]), "+f"(d[1]), "+f"(d[2]), "+f"(d[3])
        : "r"(a[0]), "r"(a[1]), "r"(a[2]), "r"(a[3]), "r"(b[0]), "r"(b[1]));
}
// ---- MUFU activations (rel err ~1e-7) ----
__device__ __forceinline__ float ex2a(float x) { float y; asm("ex2.approx.f32 %0, %1;" : "=f"(y) : "f"(x)); return y; }
__device__ __forceinline__ float rcpa(float x) { float y; asm("rcp.approx.f32 %0, %1;" : "=f"(y) : "f"(x)); return y; }
__device__ __forceinline__ float sigf(float x)  { return rcpa(1.0f + ex2a(-1.4426950408889634f * x)); }
__device__ __forceinline__ float tanhf_(float x){ return fmaf(2.0f, rcpa(1.0f + ex2a(-2.8853900817779268f * x)), -1.0f); }

__device__ __forceinline__ uint pk2h(float a, float b) {
    __half2 p = __floats2half2_rn(a, b);
    uint u; memcpy(&u, &p, 4); return u;
}
// A tile: 64 rows x 256 k fp16; atoms 8r x 64k; SW128 swizzle (32KB)
__device__ __forceinline__ uint a_off(int r, int k) {
    uint b = (uint)((((r >> 3) + (k >> 6) * 8) << 10) + ((r & 7) << 7) + ((k & 63) << 1));
    return b ^ ((b >> 3) & 0x70);
}
// W image: 512 n x 64 kcol fp16; atoms 8n x 64k (64KB)
__device__ __forceinline__ uint w_off(int n, int k) {
    uint b = (uint)(((n >> 3) << 10) + ((n & 7) << 7) + (k << 1));
    return b ^ ((b >> 3) & 0x70);
}

// ============ W prep: exact fp16 hi/lo split into 8 combined images ============
extern "C" __global__ void prep_kernel(const float* __restrict__ W_ih,
                                       const float* __restrict__ W_hh)
{
    int i = blockIdx.x * blockDim.x + threadIdx.x;   // 512*256
    if (i >= 512 * 256) return;
    int n = i >> 8, gk = i & 255;                    // gk: global K (x 0..127, h 128..255)
    float w = (gk < 128) ? W_ih[n * 128 + gk] : W_hh[n * 128 + (gk - 128)];
    __half hi = __float2half_rn(w);
    __half lo = __float2half_rn(w - __half2float(hi));
    int job = gk >> 5, kk = gk & 31;
    unsigned char* img = wblob + (size_t)job * 65536;
    *(__half*)(img + w_off(n, kk))      = hi;
    *(__half*)(img + w_off(n, kk + 32)) = lo;
}

// ============ fused LSTM recurrence (mma.sync fp16, W-split 2-term) ============
extern "C" __global__ void __launch_bounds__(NTH, 1)
lstm_mma_kernel(const float* __restrict__ x,
                const float* __restrict__ b_ih,
                const float* __restrict__ b_hh)
{
    extern __shared__ __align__(1024) char sm[];
    const uint smb  = smem_u32(sm);
    const int tid   = threadIdx.x;
    const int lane  = tid & 31;
    const int warp  = tid >> 5;       // n-slice: 8 cols per gate
    const int graph0 = blockIdx.x * MM;

    // ldmatrix lane address components (proven layout from R7)
    const int rA    = (lane & 7);
    const int mHalf = (lane >> 3) & 1;
    const int aKsel = (lane >> 4) << 4;
    const uint aPre = (uint)(rA << 7);
    const uint swA  = (uint)(rA << 4);
    const int lb    = lane & 15;
    const uint bPre = (uint)((lb & 7) << 7) + ((uint)warp << 10);
    const uint swB  = (uint)((lb & 7) << 4);
    const int bKsel = ((lb >> 3) & 1) << 4;
    const int jj   = (lane & 3) << 1;
    const int j0   = (warp << 3) + jj;
    const int rowq = lane >> 2;

    // bias seeds
    float bseed[4][2];
    #pragma unroll
    for (int gt = 0; gt < 4; gt++) {
        bseed[gt][0] = b_ih[gt * 128 + j0]     + b_hh[gt * 128 + j0];
        bseed[gt][1] = b_ih[gt * 128 + j0 + 1] + b_hh[gt * 128 + j0 + 1];
    }

    // zero h-region of A (k 128..255 = atoms 16..31 = bytes [16384,32768))
    #pragma unroll
    for (int it = 0; it < 4; it++)
        ((ull*)(sm + S_A + 16384))[tid + it * NTH] = 0ull;

    float creg[4][4];
    #pragma unroll
    for (int a = 0; a < 4; a++)
        #pragma unroll
        for (int b = 0; b < 4; b++) creg[a][b] = 0.0f;

    for (int t = 0; t < L; t++) {
        // prefetch W image 0 (overlaps x staging)
        {
            const char* src = (const char*)wblob + tid * 16;
            uint dst = smb + S_WB0 + tid * 16;
            #pragma unroll
            for (int it = 0; it < 8; it++)
                CP_ASYNC16(dst + it * 8192, src + it * 8192);
            CP_COMMIT();
        }
        // stage x_t: 64 graphs x 128 fp32 -> A k[0..127] fp16
        #pragma unroll
        for (int it = 0; it < 4; it++) {
            int idx = tid + it * NTH;
            int g = idx >> 5, v = idx & 31;
            float4 xv = *(const float4*)(x + ((size_t)(graph0 + g) * L + t) * HD + v * 4);
            *(ull*)(sm + S_A + a_off(g, v * 4)) =
                (ull)pk2h(xv.x, xv.y) | ((ull)pk2h(xv.z, xv.w) << 32);
        }

        // accumulators seeded with bias
        float acc[4][4][4];
        #pragma unroll
        for (int mt = 0; mt < 4; mt++)
            #pragma unroll
            for (int gt = 0; gt < 4; gt++) {
                acc[mt][gt][0] = bseed[gt][0]; acc[mt][gt][1] = bseed[gt][1];
                acc[mt][gt][2] = bseed[gt][0]; acc[mt][gt][3] = bseed[gt][1];
            }
        __syncthreads();   // x staged; prior-step h writes ordered by end-of-step sync

        // ---- 8 jobs (k32 slices), combined Whi|Wlo image, double-buffered ----
        for (int j = 0; j < 8; j++) {
            if (j + 1 < 8) {
                const char* src = (const char*)wblob + (size_t)(j + 1) * 65536 + tid * 16;
                uint dst = smb + ((j + 1) & 1 ? S_WB1 : S_WB0) + tid * 16;
                #pragma unroll
                for (int it = 0; it < 8; it++)
                    CP_ASYNC16(dst + it * 8192, src + it * 8192);
                CP_COMMIT();
                CP_WAIT(1);
            } else {
                CP_WAIT(0);
            }
            __syncthreads();   // image j visible

            const uint wb = smb + ((j & 1) ? S_WB1 : S_WB0);
            const int kq = j >> 1;                       // A atom-col
            const uint aAtomBase = (uint)((mHalf + kq * 8) << 10);

            #pragma unroll
            for (int ks = 0; ks < 2; ks++) {             // k16 slices within job
                const int kr = ((j & 1) << 1) + ks;      // k16 within A atom-col
                // B frags for all 4 gates, hi and lo halves of the image
                uint bh[4][2], bl[4][2];
                const uint bLowH = (uint)((ks << 5) + bKsel) ^ swB;
                const uint bLowL = (uint)(64 + (ks << 5) + bKsel) ^ swB;
                #pragma unroll
                for (int gt = 0; gt < 4; gt++) {
                    ldmx2(bh[gt], wb + (uint)(gt << 14) + bPre + bLowH);
                    ldmx2(bl[gt], wb + (uint)(gt << 14) + bPre + bLowL);
                }
                const uint aLow = (uint)((kr << 5) + aKsel) ^ swA;
                #pragma unroll
                for (int mt = 0; mt < 4; mt++) {
                    uint ah[4];
                    ldmx4(ah, smb + S_A + aAtomBase + (uint)(mt << 11) + aPre + aLow);
                    #pragma unroll
                    for (int gt = 0; gt < 4; gt++) {
                        mma16816(acc[mt][gt], ah, bh[gt]);
                        mma16816(acc[mt][gt], ah, bl[gt]);
                    }
                }
            }
            __syncthreads();   // buffer free for next refill
        }

        // ---- epilogue: lane-local LSTM update; h -> A fp16 + hs_buf fp32 ----
        #pragma unroll
        for (int mt = 0; mt < 4; mt++) {
            #pragma unroll
            for (int rg = 0; rg < 2; rg++) {
                float h2[2];
                #pragma unroll
                for (int cp = 0; cp < 2; cp++) {
                    const int fr = rg * 2 + cp;
                    float iv = sigf (acc[mt][0][fr]);
                    float fv = sigf (acc[mt][1][fr]);
                    float gv = tanhf_(acc[mt][2][fr]);
                    float ov = sigf (acc[mt][3][fr]);
                    float c  = fv * creg[mt][fr] + iv * gv;
                    creg[mt][fr] = c;
                    h2[cp] = ov * tanhf_(c);
                }
                const int g = mt * 16 + rg * 8 + rowq;
                *(uint*)(sm + S_A + a_off(g, 128 + j0)) = pk2h(h2[0], h2[1]);
                *(float2*)(hs_buf + ((size_t)(graph0 + g) * L + t) * HD + j0)
                    = make_float2(h2[0], h2[1]);
            }
        }
        __syncthreads();   // h writes visible before next step's MMAs
    }
}

// ============ attention pooling: single pass over hs_buf ============
#define AG 4   // graphs per CTA
extern "C" __global__ void __launch_bounds__(256)
att_kernel(const float* __restrict__ W_att, const float* __restrict__ b_att,
           float* __restrict__ out)
{
    extern __shared__ float s[];
    float* Hs = s;                 // [4][64][128] = 32768 floats
    float* Sc = s + 32768;         // [4][64]
    float* Pp = s + 33024;         // [8][128]
    const int tid = threadIdx.x, lane = tid & 31, warp = tid >> 5;
    const int graph0 = blockIdx.x * AG;
    const float batt = b_att[0];
    const float4 wa4 = *(const float4*)(W_att + lane * 4);

    // stage h + compute scores in the same pass (coalesced, MLP deep)
    #pragma unroll 4
    for (int it = 0; it < 32; it++) {
        const int g = it >> 3;
        const int t = (it & 7) * 8 + warp;
        float4 hv = *(const float4*)(hs_buf + ((size_t)(graph0 + g) * L + t) * HD + lane * 4);
        *(float4*)(Hs + g * 8192 + t * 128 + lane * 4) = hv;
        float d = hv.x * wa4.x + hv.y * wa4.y + hv.z * wa4.z + hv.w * wa4.w;
        #pragma unroll
        for (int o = 16; o; o >>= 1)
            d += __shfl_xor_sync(0xffffffffu, d, o);
        if (lane == 0) Sc[g * 64 + t] = d + batt;
    }
    __syncthreads();

    // softmax per graph (warps 0..3)
    if (warp < 4) {
        const int g = warp;
        float s1 = Sc[g * 64 + lane], s2 = Sc[g * 64 + 32 + lane];
        float m = fmaxf(s1, s2);
        #pragma unroll
        for (int o = 16; o; o >>= 1)
            m = fmaxf(m, __shfl_xor_sync(0xffffffffu, m, o));
        float e1 = ex2a(1.4426950408889634f * (s1 - m));
        float e2 = ex2a(1.4426950408889634f * (s2 - m));
        float z = e1 + e2;
        #pragma unroll
        for (int o = 16; o; o >>= 1)
            z += __shfl_xor_sync(0xffffffffu, z, o);
        float inv = rcpa(z);
        Sc[g * 64 + lane] = e1 * inv;
        Sc[g * 64 + 32 + lane] = e2 * inv;
    }
    __syncthreads();

    // weighted sum: warp w -> graph w>>1, t-half w&1
    {
        const int g = warp >> 1;
        float4 a4 = make_float4(0.f, 0.f, 0.f, 0.f);
        #pragma unroll 4
        for (int tt = 0; tt < 32; tt++) {
            const int t = (warp & 1) * 32 + tt;
            float wt = Sc[g * 64 + t];
            float4 hv = *(const float4*)(Hs + g * 8192 + t * 128 + lane * 4);
            a4.x = fmaf(wt, hv.x, a4.x);
            a4.y = fmaf(wt, hv.y, a4.y);
            a4.z = fmaf(wt, hv.z, a4.z);
            a4.w = fmaf(wt, hv.w, a4.w);
        }
        *(float4*)(Pp + warp * 128 + lane * 4) = a4;
    }
    __syncthreads();

    // combine halves and write out
    {
        const int g = tid >> 6, q = tid & 63;
        float v0 = Pp[(2 * g) * 128 + 2 * q]     + Pp[(2 * g + 1) * 128 + 2 * q];
        float v1 = Pp[(2 * g) * 128 + 2 * q + 1] + Pp[(2 * g + 1) * 128 + 2 * q + 1];
        *(float2*)(out + (size_t)(graph0 + g) * HD + 2 * q) = make_float2(v0, v1);
    }
}

extern "C" void kernel_launch(void* const* d_in, const int* in_sizes, int n_in,
                              void* d_out, int out_size)
{
    const float* x     = (const float*)d_in[0];
    // d_in[1] = batch (arange(N)//L), unused
    const float* W_ih  = (const float*)d_in[2];
    const float* W_hh  = (const float*)d_in[3];
    const float* b_ih  = (const float*)d_in[4];
    const float* b_hh  = (const float*)d_in[5];
    const float* W_att = (const float*)d_in[6];
    const float* b_att = (const float*)d_in[7];
    float* out = (float*)d_out;

    prep_kernel<<<512, 256>>>(W_ih, W_hh);
    cudaFuncSetAttribute(lstm_mma_kernel,
                         cudaFuncAttributeMaxDynamicSharedMemorySize, S_TOT);
    lstm_mma_kernel<<<NGR / MM, NTH, S_TOT>>>(x, b_ih, b_hh);
    const int att_smem = (32768 + 256 + 1024) * 4;   // Hs + Sc + Pp
    cudaFuncSetAttribute(att_kernel,
                         cudaFuncAttributeMaxDynamicSharedMemorySize, att_smem);
    att_kernel<<<NGR / AG, 256, att_smem>>>(W_att, b_att, out);
}

// round 11
// speedup vs baseline: 2.0054x; 1.4735x over previous
#include <cuda_runtime.h>
#include <cuda_fp16.h>
#include <cstdint>
#include <string.h>

typedef unsigned long long ull;
typedef unsigned int uint;

#define L    64
#define NGR  8192
#define HD   128
#define MM   64             // graphs per CTA
#define NTH  512            // 16 warps

// ---- smem byte offsets ----
#define S_A    0            // A: 64 rows x 256 k fp16, SW128 blocked (32KB)
#define S_WB0  32768        // W image buf 0 (64KB)
#define S_WB1  98304        // W image buf 1 (64KB)
#define S_TOT  163840

// W images: 4 jobs (k64 slices of K=256). Each: [512 n][64 k] fp16,
// SW128 blocked, 64KB.
__device__ __align__(128) unsigned char wblob[4 * 65536];
__device__ float hs_buf[(size_t)NGR * L * HD];   // 256MB hidden states

// ---- PTX helpers (base PTX; no tcgen05 on this toolchain) ----
__device__ __forceinline__ uint smem_u32(const void* p) {
    uint a; asm("{ .reg .u64 t; cvta.to.shared.u64 t, %1; cvt.u32.u64 %0, t; }"
                : "=r"(a) : "l"(p));
    return a;
}
#define CP_ASYNC16(dst, src) \
    asm volatile("cp.async.cg.shared.global [%0], [%1], 16;" :: "r"(dst), "l"(src))
#define CP_COMMIT() asm volatile("cp.async.commit_group;" ::: "memory")
#define CP_WAIT(n)  asm volatile("cp.async.wait_group %0;" :: "n"(n) : "memory")

__device__ __forceinline__ void ldmx4(uint* r, uint addr) {
    asm volatile("ldmatrix.sync.aligned.m8n8.x4.shared.b16 {%0,%1,%2,%3}, [%4];"
        : "=r"(r[0]), "=r"(r[1]), "=r"(r[2]), "=r"(r[3]) : "r"(addr));
}
// W stored K-major: non-trans ldmatrix yields the .col B fragment directly.
__device__ __forceinline__ void ldmx2(uint* r, uint addr) {
    asm volatile("ldmatrix.sync.aligned.m8n8.x2.shared.b16 {%0,%1}, [%2];"
        : "=r"(r[0]), "=r"(r[1]) : "r"(addr));
}
__device__ __forceinline__ void mma16816(float* d, const uint* a, const uint* b) {
    asm volatile(
        "mma.sync.aligned.m16n8k16.row.col.f32.f16.f16.f32 "
        "{%0,%1,%2,%3}, {%4,%5,%6,%7}, {%8,%9}, {%0,%1,%2,%3};"
        : "+f"(d[0]), "+f"(d[1]), "+f"(d[2]), "+f"(d[3])
        : "r"(a[0]), "r"(a[1]), "r"(a[2]), "r"(a[3]), "r"(b[0]), "r"(b[1]));
}
// ---- MUFU activations (rel err ~1e-7) ----
__device__ __forceinline__ float ex2a(float x) { float y; asm("ex2.approx.f32 %0, %1;" : "=f"(y) : "f"(x)); return y; }
__device__ __forceinline__ float rcpa(float x) { float y; asm("rcp.approx.f32 %0, %1;" : "=f"(y) : "f"(x)); return y; }
__device__ __forceinline__ float sigf(float x)  { return rcpa(1.0f + ex2a(-1.4426950408889634f * x)); }
__device__ __forceinline__ float tanhf_(float x){ return fmaf(2.0f, rcpa(1.0f + ex2a(-2.8853900817779268f * x)), -1.0f); }

__device__ __forceinline__ uint pk2h(float a, float b) {
    __half2 p = __floats2half2_rn(a, b);
    uint u; memcpy(&u, &p, 4); return u;
}
// A tile: 64 rows x 256 k fp16; atoms 8r x 64k; SW128 swizzle (32KB)
__device__ __forceinline__ uint a_off(int r, int k) {
    uint b = (uint)((((r >> 3) + (k >> 6) * 8) << 10) + ((r & 7) << 7) + ((k & 63) << 1));
    return b ^ ((b >> 3) & 0x70);
}
// W image: 512 n x 64 k fp16; atoms 8n x 64k (64KB)
__device__ __forceinline__ uint w_off(int n, int k) {
    uint b = (uint)(((n >> 3) << 10) + ((n & 7) << 7) + (k << 1));
    return b ^ ((b >> 3) & 0x70);
}

// ============ W prep: fp16 round, swizzle into 4 k64 images ============
extern "C" __global__ void prep_kernel(const float* __restrict__ W_ih,
                                       const float* __restrict__ W_hh)
{
    int i = blockIdx.x * blockDim.x + threadIdx.x;   // 512*256
    if (i >= 512 * 256) return;
    int n = i >> 8, gk = i & 255;                    // gk: x 0..127, h 128..255
    float w = (gk < 128) ? W_ih[n * 128 + gk] : W_hh[n * 128 + (gk - 128)];
    int job = gk >> 6, kk = gk & 63;
    *(__half*)(wblob + (size_t)job * 65536 + w_off(n, kk)) = __float2half_rn(w);
}

// ============ fused LSTM recurrence (mma.sync fp16) ============
extern "C" __global__ void __launch_bounds__(NTH, 1)
lstm_mma_kernel(const float* __restrict__ x,
                const float* __restrict__ b_ih,
                const float* __restrict__ b_hh)
{
    extern __shared__ __align__(1024) char sm[];
    const uint smb  = smem_u32(sm);
    const int tid   = threadIdx.x;
    const int lane  = tid & 31;
    const int warp  = tid >> 5;       // n-slice: 8 cols per gate
    const int graph0 = blockIdx.x * MM;

    // ldmatrix lane address components (proven layout from R7/R10)
    const int rA    = (lane & 7);
    const int mHalf = (lane >> 3) & 1;
    const int aKsel = (lane >> 4) << 4;
    const uint aPre = (uint)(rA << 7);
    const uint swA  = (uint)(rA << 4);
    const int lb    = lane & 15;
    const uint bPre = (uint)((lb & 7) << 7) + ((uint)warp << 10);
    const uint swB  = (uint)((lb & 7) << 4);
    const int bKsel = ((lb >> 3) & 1) << 4;
    const int jj   = (lane & 3) << 1;
    const int j0   = (warp << 3) + jj;
    const int rowq = lane >> 2;

    // bias seeds
    float bseed[4][2];
    #pragma unroll
    for (int gt = 0; gt < 4; gt++) {
        bseed[gt][0] = b_ih[gt * 128 + j0]     + b_hh[gt * 128 + j0];
        bseed[gt][1] = b_ih[gt * 128 + j0 + 1] + b_hh[gt * 128 + j0 + 1];
    }

    // zero h-region of A (k 128..255 = bytes [16384,32768))
    #pragma unroll
    for (int it = 0; it < 4; it++)
        ((ull*)(sm + S_A + 16384))[tid + it * NTH] = 0ull;

    float creg[4][4];
    #pragma unroll
    for (int a = 0; a < 4; a++)
        #pragma unroll
        for (int b = 0; b < 4; b++) creg[a][b] = 0.0f;

    for (int t = 0; t < L; t++) {
        // prefetch W image 0 (overlaps x staging)
        {
            const char* src = (const char*)wblob + tid * 16;
            uint dst = smb + S_WB0 + tid * 16;
            #pragma unroll
            for (int it = 0; it < 8; it++)
                CP_ASYNC16(dst + it * 8192, src + it * 8192);
            CP_COMMIT();
        }
        // stage x_t: 64 graphs x 128 fp32 -> A k[0..127] fp16
        #pragma unroll
        for (int it = 0; it < 4; it++) {
            int idx = tid + it * NTH;
            int g = idx >> 5, v = idx & 31;
            float4 xv = *(const float4*)(x + ((size_t)(graph0 + g) * L + t) * HD + v * 4);
            *(ull*)(sm + S_A + a_off(g, v * 4)) =
                (ull)pk2h(xv.x, xv.y) | ((ull)pk2h(xv.z, xv.w) << 32);
        }

        // accumulators seeded with bias
        float acc[4][4][4];
        #pragma unroll
        for (int mt = 0; mt < 4; mt++)
            #pragma unroll
            for (int gt = 0; gt < 4; gt++) {
                acc[mt][gt][0] = bseed[gt][0]; acc[mt][gt][1] = bseed[gt][1];
                acc[mt][gt][2] = bseed[gt][0]; acc[mt][gt][3] = bseed[gt][1];
            }
        __syncthreads();   // x staged; prior-step h writes ordered

        // ---- 4 jobs (k64 slices), double-buffered ----
        for (int j = 0; j < 4; j++) {
            if (j + 1 < 4) {
                const char* src = (const char*)wblob + (size_t)(j + 1) * 65536 + tid * 16;
                uint dst = smb + ((j + 1) & 1 ? S_WB1 : S_WB0) + tid * 16;
                #pragma unroll
                for (int it = 0; it < 8; it++)
                    CP_ASYNC16(dst + it * 8192, src + it * 8192);
                CP_COMMIT();
                CP_WAIT(1);
            } else {
                CP_WAIT(0);
            }
            __syncthreads();   // image j visible

            const uint wb = smb + ((j & 1) ? S_WB1 : S_WB0);
            const uint aAtomBase = (uint)((mHalf + j * 8) << 10);

            #pragma unroll
            for (int ks = 0; ks < 4; ks++) {             // k16 slices of this k64
                uint bfr[4][2];
                const uint bLow = (uint)((ks << 5) + bKsel) ^ swB;
                #pragma unroll
                for (int gt = 0; gt < 4; gt++)
                    ldmx2(bfr[gt], wb + (uint)(gt << 14) + bPre + bLow);
                const uint aLow = (uint)((ks << 5) + aKsel) ^ swA;
                #pragma unroll
                for (int mt = 0; mt < 4; mt++) {
                    uint ah[4];
                    ldmx4(ah, smb + S_A + aAtomBase + (uint)(mt << 11) + aPre + aLow);
                    #pragma unroll
                    for (int gt = 0; gt < 4; gt++)
                        mma16816(acc[mt][gt], ah, bfr[gt]);
                }
            }
            __syncthreads();   // buffer free for next refill
        }

        // ---- epilogue: lane-local LSTM update; h -> A fp16 + hs_buf fp32 ----
        #pragma unroll
        for (int mt = 0; mt < 4; mt++) {
            #pragma unroll
            for (int rg = 0; rg < 2; rg++) {
                float h2[2];
                #pragma unroll
                for (int cp = 0; cp < 2; cp++) {
                    const int fr = rg * 2 + cp;
                    float iv = sigf (acc[mt][0][fr]);
                    float fv = sigf (acc[mt][1][fr]);
                    float gv = tanhf_(acc[mt][2][fr]);
                    float ov = sigf (acc[mt][3][fr]);
                    float c  = fv * creg[mt][fr] + iv * gv;
                    creg[mt][fr] = c;
                    h2[cp] = ov * tanhf_(c);
                }
                const int g = mt * 16 + rg * 8 + rowq;
                *(uint*)(sm + S_A + a_off(g, 128 + j0)) = pk2h(h2[0], h2[1]);
                __stcs((float2*)(hs_buf + ((size_t)(graph0 + g) * L + t) * HD + j0),
                       make_float2(h2[0], h2[1]));
            }
        }
        __syncthreads();   // h writes visible before next step's MMAs
    }
}

// ============ attention pooling: single pass over hs_buf ============
#define AG 4   // graphs per CTA
extern "C" __global__ void __launch_bounds__(256)
att_kernel(const float* __restrict__ W_att, const float* __restrict__ b_att,
           float* __restrict__ out)
{
    extern __shared__ float s[];
    float* Hs = s;                 // [4][64][128] = 32768 floats
    float* Sc = s + 32768;         // [4][64]
    float* Pp = s + 33024;         // [8][128]
    const int tid = threadIdx.x, lane = tid & 31, warp = tid >> 5;
    const int graph0 = blockIdx.x * AG;
    const float batt = b_att[0];
    const float4 wa4 = *(const float4*)(W_att + lane * 4);

    // stage h + compute scores in the same pass (coalesced, MLP deep)
    #pragma unroll 4
    for (int it = 0; it < 32; it++) {
        const int g = it >> 3;
        const int t = (it & 7) * 8 + warp;
        float4 hv = __ldcs((const float4*)(hs_buf +
                        ((size_t)(graph0 + g) * L + t) * HD + lane * 4));
        *(float4*)(Hs + g * 8192 + t * 128 + lane * 4) = hv;
        float d = hv.x * wa4.x + hv.y * wa4.y + hv.z * wa4.z + hv.w * wa4.w;
        #pragma unroll
        for (int o = 16; o; o >>= 1)
            d += __shfl_xor_sync(0xffffffffu, d, o);
        if (lane == 0) Sc[g * 64 + t] = d + batt;
    }
    __syncthreads();

    // softmax per graph (warps 0..3)
    if (warp < 4) {
        const int g = warp;
        float s1 = Sc[g * 64 + lane], s2 = Sc[g * 64 + 32 + lane];
        float m = fmaxf(s1, s2);
        #pragma unroll
        for (int o = 16; o; o >>= 1)
            m = fmaxf(m, __shfl_xor_sync(0xffffffffu, m, o));
        float e1 = ex2a(1.4426950408889634f * (s1 - m));
        float e2 = ex2a(1.4426950408889634f * (s2 - m));
        float z = e1 + e2;
        #pragma unroll
        for (int o = 16; o; o >>= 1)
            z += __shfl_xor_sync(0xffffffffu, z, o);
        float inv = rcpa(z);
        Sc[g * 64 + lane] = e1 * inv;
        Sc[g * 64 + 32 + lane] = e2 * inv;
    }
    __syncthreads();

    // weighted sum: warp w -> graph w>>1, t-half w&1
    {
        const int g = warp >> 1;
        float4 a4 = make_float4(0.f, 0.f, 0.f, 0.f);
        #pragma unroll 4
        for (int tt = 0; tt < 32; tt++) {
            const int t = (warp & 1) * 32 + tt;
            float wt = Sc[g * 64 + t];
            float4 hv = *(const float4*)(Hs + g * 8192 + t * 128 + lane * 4);
            a4.x = fmaf(wt, hv.x, a4.x);
            a4.y = fmaf(wt, hv.y, a4.y);
            a4.z = fmaf(wt, hv.z, a4.z);
            a4.w = fmaf(wt, hv.w, a4.w);
        }
        *(float4*)(Pp + warp * 128 + lane * 4) = a4;
    }
    __syncthreads();

    // combine halves and write out
    {
        const int g = tid >> 6, q = tid & 63;
        float v0 = Pp[(2 * g) * 128 + 2 * q]     + Pp[(2 * g + 1) * 128 + 2 * q];
        float v1 = Pp[(2 * g) * 128 + 2 * q + 1] + Pp[(2 * g + 1) * 128 + 2 * q + 1];
        *(float2*)(out + (size_t)(graph0 + g) * HD + 2 * q) = make_float2(v0, v1);
    }
}

extern "C" void kernel_launch(void* const* d_in, const int* in_sizes, int n_in,
                              void* d_out, int out_size)
{
    const float* x     = (const float*)d_in[0];
    // d_in[1] = batch (arange(N)//L), unused
    const float* W_ih  = (const float*)d_in[2];
    const float* W_hh  = (const float*)d_in[3];
    const float* b_ih  = (const float*)d_in[4];
    const float* b_hh  = (const float*)d_in[5];
    const float* W_att = (const float*)d_in[6];
    const float* b_att = (const float*)d_in[7];
    float* out = (float*)d_out;

    prep_kernel<<<512, 256>>>(W_ih, W_hh);
    cudaFuncSetAttribute(lstm_mma_kernel,
                         cudaFuncAttributeMaxDynamicSharedMemorySize, S_TOT);
    lstm_mma_kernel<<<NGR / MM, NTH, S_TOT>>>(x, b_ih, b_hh);
    const int att_smem = (32768 + 256 + 1024) * 4;   // Hs + Sc + Pp
    cudaFuncSetAttribute(att_kernel,
                         cudaFuncAttributeMaxDynamicSharedMemorySize, att_smem);
    att_kernel<<<NGR / AG, 256, att_smem>>>(W_att, b_att, out);
}